// round 1
// baseline (speedup 1.0000x reference)
#include <cuda_runtime.h>
#include <cuda_bf16.h>

#define BLOCK 256
#define GRID  304          // 152 SMs * 2 CTAs
#define MAX_MOL 4096

// ---------------------------------------------------------------------------
// Kernel 1: initialize the output buffer.
//   Layout A (out_size > n_mol): [species as float (n_species)] [energies (n_mol)]
//   Layout B (out_size == n_mol): [energies (n_mol)]
// ---------------------------------------------------------------------------
__global__ void init_kernel(const int* __restrict__ species,
                            const float* __restrict__ energies,
                            float* __restrict__ out,
                            int n_species, int n_mol, int with_species) {
    int i = blockIdx.x * blockDim.x + threadIdx.x;
    if (with_species) {
        if (i < n_species) out[i] = (float)species[i];
        if (i < n_mol)     out[n_species + i] = energies[i];
    } else {
        if (i < n_mol)     out[i] = energies[i];
    }
}

// ---------------------------------------------------------------------------
// Kernel 2: pair loop + per-CTA smem histogram + global flush.
// ---------------------------------------------------------------------------
__global__ __launch_bounds__(BLOCK) void srb_kernel(
    const int*   __restrict__ idx12,      // [2, n_pairs] flattened
    const float* __restrict__ dist,       // [n_pairs] (angstrom)
    const int*   __restrict__ species,    // [n_mol * n_atoms]
    const float* __restrict__ ep,         // [16] exp_prefactor
    const float* __restrict__ df,         // [16] distances_factor
    float*       __restrict__ out_energy, // [n_mol]
    int n_pairs, int shift, int n_atoms, int n_mol)
{
    __shared__ float hist[MAX_MOL];
    __shared__ float s_pre[16];
    __shared__ float s_df[16];

    if (threadIdx.x < 16) {
        s_pre[threadIdx.x] = ep[threadIdx.x];
        s_df[threadIdx.x]  = df[threadIdx.x];
    }
    for (int i = threadIdx.x; i < n_mol; i += BLOCK) hist[i] = 0.0f;
    __syncthreads();

    const float A2B     = 1.8897261258369282f;
    const float rc      = 5.2f * A2B;
    const float inv_rc2 = 1.0f / (rc * rc);

    const int stride = gridDim.x * BLOCK;
    for (int p = blockIdx.x * BLOCK + threadIdx.x; p < n_pairs; p += stride) {
        int   i1 = idx12[p];
        int   i2 = idx12[p + n_pairs];
        float d  = dist[p] * A2B;

        int   t  = species[i1] * 4 + species[i2];
        float x2 = d * d * inv_rc2;

        if (x2 < 1.0f) {
            float fc  = __expf(1.0f - 1.0f / (1.0f - x2));
            float srb = s_pre[t] * __expf(s_df[t] * d) * fc;
            unsigned mol = (shift >= 0) ? ((unsigned)i1 >> shift)
                                        : ((unsigned)i1 / (unsigned)n_atoms);
            atomicAdd(&hist[mol], srb);
        }
    }
    __syncthreads();

    for (int i = threadIdx.x; i < n_mol; i += BLOCK) {
        float v = hist[i];
        if (v != 0.0f) atomicAdd(&out_energy[i], v);
    }
}

// ---------------------------------------------------------------------------
// Launch. Inputs (metadata order):
//   0: species          int32  [n_mol * n_atoms]
//   1: energies         float  [n_mol]
//   2: atom_index12     int32  [2 * n_pairs]
//   3: distances        float  [n_pairs]
//   4: exp_prefactor    float  [16]
//   5: distances_factor float  [16]
// ---------------------------------------------------------------------------
extern "C" void kernel_launch(void* const* d_in, const int* in_sizes, int n_in,
                              void* d_out, int out_size) {
    const int*   species  = (const int*)  d_in[0];
    const float* energies = (const float*)d_in[1];
    const int*   idx12    = (const int*)  d_in[2];
    const float* dist     = (const float*)d_in[3];
    const float* ep       = (const float*)d_in[4];
    const float* df       = (const float*)d_in[5];

    int n_species = in_sizes[0];
    int n_mol     = in_sizes[1];
    int n_pairs   = in_sizes[3];
    int n_atoms   = n_species / n_mol;

    int with_species = (out_size > n_mol) ? 1 : 0;
    float* out        = (float*)d_out;
    float* out_energy = with_species ? (out + n_species) : out;

    // power-of-two fast path for mol index
    int shift = -1;
    if (n_atoms > 0 && (n_atoms & (n_atoms - 1)) == 0) {
        shift = 0;
        int v = n_atoms;
        while (v > 1) { v >>= 1; shift++; }
    }

    int init_n = (n_species > n_mol ? n_species : n_mol);
    init_kernel<<<(init_n + 255) / 256, 256>>>(species, energies, out,
                                               n_species, n_mol, with_species);
    srb_kernel<<<GRID, BLOCK>>>(idx12, dist, species, ep, df, out_energy,
                                n_pairs, shift, n_atoms, n_mol);
}

// round 2
// speedup vs baseline: 6.0496x; 6.0496x over previous
#include <cuda_runtime.h>
#include <cuda_bf16.h>

#define BLOCK 1024
#define GRID  304           // 152 SMs * 2 CTAs -> 64 warps/SM
#define MAX_MOL 4096
#define PACK_CAP (4 * 1024 * 1024)   // packed bytes: supports up to 16M atoms

__device__ unsigned char g_packed[PACK_CAP];

// ---------------------------------------------------------------------------
// Kernel 0: pack species (0..3) into 2-bit entries, 4 atoms per byte.
// ---------------------------------------------------------------------------
__global__ void pack_kernel(const int* __restrict__ sp, int n) {
    int i = blockIdx.x * blockDim.x + threadIdx.x;  // one output byte
    int nb = (n + 3) >> 2;
    if (i < nb) {
        int base = i * 4;
        unsigned v = 0;
#pragma unroll
        for (int k = 0; k < 4; k++) {
            int a = (base + k < n) ? sp[base + k] : 0;
            v |= ((unsigned)a & 3u) << (2 * k);
        }
        g_packed[i] = (unsigned char)v;
    }
}

// ---------------------------------------------------------------------------
// Kernel 1: initialize output.
//   Layout A (out_size > n_mol): [species as float (n_species)] [energies (n_mol)]
//   Layout B (out_size == n_mol): [energies (n_mol)]
// ---------------------------------------------------------------------------
__global__ void init_kernel(const int* __restrict__ species,
                            const float* __restrict__ energies,
                            float* __restrict__ out,
                            int n_species, int n_mol, int with_species) {
    int i = blockIdx.x * blockDim.x + threadIdx.x;
    if (with_species) {
        if (i < n_species) out[i] = (float)species[i];
        if (i < n_mol)     out[n_species + i] = energies[i];
    } else {
        if (i < n_mol)     out[i] = energies[i];
    }
}

// ---------------------------------------------------------------------------
// Kernel 2: pair loop, vectorized x4, 2-bit species gathers, smem histogram.
// ---------------------------------------------------------------------------
__device__ __forceinline__ unsigned spec2(int idx) {
    unsigned char b = __ldg(&g_packed[idx >> 2]);
    return ((unsigned)b >> ((idx & 3) * 2)) & 3u;
}

template <bool POW2>
__global__ __launch_bounds__(BLOCK) void srb_kernel(
    const int*   __restrict__ idx12,      // [2, n_pairs]
    const float* __restrict__ dist,       // [n_pairs]
    const float* __restrict__ ep,         // [16]
    const float* __restrict__ df,         // [16]
    float*       __restrict__ out_energy, // [n_mol]
    int n_pairs, int shift, int n_atoms, int n_mol)
{
    __shared__ float hist[MAX_MOL];
    __shared__ float s_pre[16];
    __shared__ float s_df[16];

    if (threadIdx.x < 16) {
        s_pre[threadIdx.x] = ep[threadIdx.x];
        s_df[threadIdx.x]  = df[threadIdx.x];
    }
    for (int i = threadIdx.x; i < n_mol; i += BLOCK) hist[i] = 0.0f;
    __syncthreads();

    const float A2B     = 1.8897261258369282f;
    const float rc      = 5.2f * A2B;
    const float inv_rc2 = 1.0f / (rc * rc);

    const int nvec = n_pairs >> 2;             // groups of 4 pairs
    const int4*   iv1 = (const int4*)idx12;
    const int4*   iv2 = (const int4*)(idx12 + n_pairs);
    const float4* dv  = (const float4*)dist;

    const int stride = GRID * BLOCK;
    for (int p = blockIdx.x * BLOCK + threadIdx.x; p < nvec; p += stride) {
        int4   a = __ldcs(&iv1[p]);
        int4   b = __ldcs(&iv2[p]);
        float4 w = __ldcs(&dv[p]);

        int   i1[4] = {a.x, a.y, a.z, a.w};
        int   i2[4] = {b.x, b.y, b.z, b.w};
        float dd[4] = {w.x, w.y, w.z, w.w};

        unsigned t[4];
#pragma unroll
        for (int k = 0; k < 4; k++)
            t[k] = spec2(i1[k]) * 4u + spec2(i2[k]);

#pragma unroll
        for (int k = 0; k < 4; k++) {
            float d  = dd[k] * A2B;
            float x2 = d * d * inv_rc2;
            if (x2 < 1.0f) {
                // exp(df*d) * exp(1 - 1/(1-x2)) fused into one exp
                float E   = fmaf(s_df[t[k]], d, 1.0f - __fdividef(1.0f, 1.0f - x2));
                float srb = s_pre[t[k]] * __expf(E);
                unsigned mol = POW2 ? ((unsigned)i1[k] >> shift)
                                    : ((unsigned)i1[k] / (unsigned)n_atoms);
                atomicAdd(&hist[mol], srb);
            }
        }
    }

    // scalar tail (n_pairs % 4), block 0 only
    if (blockIdx.x == 0) {
        for (int p = nvec * 4 + threadIdx.x; p < n_pairs; p += BLOCK) {
            int   i1 = idx12[p];
            int   i2 = idx12[p + n_pairs];
            float d  = dist[p] * A2B;
            unsigned tt = spec2(i1) * 4u + spec2(i2);
            float x2 = d * d * inv_rc2;
            if (x2 < 1.0f) {
                float E   = fmaf(s_df[tt], d, 1.0f - __fdividef(1.0f, 1.0f - x2));
                float srb = s_pre[tt] * __expf(E);
                unsigned mol = POW2 ? ((unsigned)i1 >> shift)
                                    : ((unsigned)i1 / (unsigned)n_atoms);
                atomicAdd(&hist[mol], srb);
            }
        }
    }
    __syncthreads();

    for (int i = threadIdx.x; i < n_mol; i += BLOCK) {
        float v = hist[i];
        if (v != 0.0f) atomicAdd(&out_energy[i], v);
    }
}

// Fallback for n_mol > MAX_MOL: global atomics directly (not expected here).
__global__ __launch_bounds__(BLOCK) void srb_global_kernel(
    const int* __restrict__ idx12, const float* __restrict__ dist,
    const float* __restrict__ ep, const float* __restrict__ df,
    float* __restrict__ out_energy, int n_pairs, int n_atoms)
{
    __shared__ float s_pre[16];
    __shared__ float s_df[16];
    if (threadIdx.x < 16) { s_pre[threadIdx.x] = ep[threadIdx.x]; s_df[threadIdx.x] = df[threadIdx.x]; }
    __syncthreads();
    const float A2B = 1.8897261258369282f;
    const float rc = 5.2f * A2B;
    const float inv_rc2 = 1.0f / (rc * rc);
    const int stride = gridDim.x * BLOCK;
    for (int p = blockIdx.x * BLOCK + threadIdx.x; p < n_pairs; p += stride) {
        int i1 = idx12[p], i2 = idx12[p + n_pairs];
        float d = dist[p] * A2B;
        unsigned t = spec2(i1) * 4u + spec2(i2);
        float x2 = d * d * inv_rc2;
        if (x2 < 1.0f) {
            float E = fmaf(s_df[t], d, 1.0f - __fdividef(1.0f, 1.0f - x2));
            atomicAdd(&out_energy[(unsigned)i1 / (unsigned)n_atoms], s_pre[t] * __expf(E));
        }
    }
}

// ---------------------------------------------------------------------------
extern "C" void kernel_launch(void* const* d_in, const int* in_sizes, int n_in,
                              void* d_out, int out_size) {
    const int*   species  = (const int*)  d_in[0];
    const float* energies = (const float*)d_in[1];
    const int*   idx12    = (const int*)  d_in[2];
    const float* dist     = (const float*)d_in[3];
    const float* ep       = (const float*)d_in[4];
    const float* df       = (const float*)d_in[5];

    int n_species = in_sizes[0];
    int n_mol     = in_sizes[1];
    int n_pairs   = in_sizes[3];
    int n_atoms   = n_species / n_mol;

    int with_species = (out_size > n_mol) ? 1 : 0;
    float* out        = (float*)d_out;
    float* out_energy = with_species ? (out + n_species) : out;

    int shift = -1;
    if (n_atoms > 0 && (n_atoms & (n_atoms - 1)) == 0) {
        shift = 0;
        int v = n_atoms;
        while (v > 1) { v >>= 1; shift++; }
    }

    int nb = (n_species + 3) >> 2;
    pack_kernel<<<(nb + 255) / 256, 256>>>(species, n_species);

    int init_n = (n_species > n_mol ? n_species : n_mol);
    init_kernel<<<(init_n + 255) / 256, 256>>>(species, energies, out,
                                               n_species, n_mol, with_species);

    if (n_mol <= MAX_MOL) {
        if (shift >= 0)
            srb_kernel<true><<<GRID, BLOCK>>>(idx12, dist, ep, df, out_energy,
                                              n_pairs, shift, n_atoms, n_mol);
        else
            srb_kernel<false><<<GRID, BLOCK>>>(idx12, dist, ep, df, out_energy,
                                               n_pairs, shift, n_atoms, n_mol);
    } else {
        srb_global_kernel<<<GRID, BLOCK>>>(idx12, dist, ep, df, out_energy,
                                           n_pairs, n_atoms);
    }
}

// round 4
// speedup vs baseline: 7.2298x; 1.1951x over previous
#include <cuda_runtime.h>
#include <cuda_bf16.h>

#define BLOCK 1024
#define GRID  304            // 152 SMs * 2 CTAs
#define MAX_MOL 4096
#define PACK_WORDS_CAP (1 << 20)     // u32 words; 16 atoms/word -> up to 16M atoms

__device__ unsigned g_packed[PACK_WORDS_CAP];

// ---------------------------------------------------------------------------
// Prep: pack species (0..3) into 2-bit entries (16/word) AND init output.
//   Layout A (out_size > n_mol): [species as float (n_species)] [energies]
//   Layout B: [energies]
// ---------------------------------------------------------------------------
__global__ void prep_kernel(const int* __restrict__ sp,
                            const float* __restrict__ energies,
                            float* __restrict__ out,
                            int n_species, int n_mol, int with_species) {
    int i = blockIdx.x * blockDim.x + threadIdx.x;
    int n_words = (n_species + 15) >> 4;

    if (i < n_words) {
        int base = i * 16;
        unsigned v = 0;
        if (base + 16 <= n_species) {
            const int4* p = (const int4*)(sp + base);
#pragma unroll
            for (int q = 0; q < 4; q++) {
                int4 s = p[q];
                v |= ((unsigned)s.x & 3u) << (2 * (q * 4 + 0));
                v |= ((unsigned)s.y & 3u) << (2 * (q * 4 + 1));
                v |= ((unsigned)s.z & 3u) << (2 * (q * 4 + 2));
                v |= ((unsigned)s.w & 3u) << (2 * (q * 4 + 3));
            }
        } else {
            for (int k = 0; k < 16 && base + k < n_species; k++)
                v |= ((unsigned)sp[base + k] & 3u) << (2 * k);
        }
        g_packed[i] = v;
    }

    if (with_species) {
        if (i < n_species) out[i] = (float)sp[i];
        if (i < n_mol)     out[n_species + i] = energies[i];
    } else {
        if (i < n_mol)     out[i] = energies[i];
    }
}

// ---------------------------------------------------------------------------
// Main kernel: pair loop, x4 vector streams, smem species table + histogram.
// Dynamic smem layout: [ hist: MAX_MOL floats ][ tbl: n_words u32 ]
// ---------------------------------------------------------------------------
__device__ __forceinline__ unsigned spec_smem(const unsigned* tbl, int idx) {
    return (tbl[idx >> 4] >> ((idx & 15) * 2)) & 3u;
}
__device__ __forceinline__ unsigned spec_gmem(int idx) {
    return (__ldg(&g_packed[idx >> 4]) >> ((idx & 15) * 2)) & 3u;
}

template <bool POW2, bool SMEM_TBL>
__global__ __launch_bounds__(BLOCK, 2) void srb_kernel(
    const int*   __restrict__ idx12,
    const float* __restrict__ dist,
    const float* __restrict__ ep,
    const float* __restrict__ df,
    float*       __restrict__ out_energy,
    int n_pairs, int shift, int n_atoms, int n_mol, int n_words)
{
    extern __shared__ unsigned char smem_raw[];
    float*    hist = (float*)smem_raw;
    unsigned* tbl  = (unsigned*)(smem_raw + MAX_MOL * sizeof(float));

    __shared__ float s_pre[16];
    __shared__ float s_df[16];

    if (threadIdx.x < 16) {
        s_pre[threadIdx.x] = ep[threadIdx.x];
        s_df[threadIdx.x]  = df[threadIdx.x];
    }
    for (int i = threadIdx.x; i < MAX_MOL; i += BLOCK) hist[i] = 0.0f;
    if (SMEM_TBL) {
        for (int i = threadIdx.x; i < n_words; i += BLOCK)
            tbl[i] = g_packed[i];
    }
    __syncthreads();

    const float A2B     = 1.8897261258369282f;
    const float rc      = 5.2f * A2B;
    const float inv_rc2 = 1.0f / (rc * rc);

    const int nvec = n_pairs >> 2;
    const int4*   iv1 = (const int4*)idx12;
    const int4*   iv2 = (const int4*)(idx12 + n_pairs);
    const float4* dv  = (const float4*)dist;

    const int stride = GRID * BLOCK;
    for (int p = blockIdx.x * BLOCK + threadIdx.x; p < nvec; p += stride) {
        int4   a = __ldcs(&iv1[p]);
        int4   b = __ldcs(&iv2[p]);
        float4 w = __ldcs(&dv[p]);

        int   i1[4] = {a.x, a.y, a.z, a.w};
        int   i2[4] = {b.x, b.y, b.z, b.w};
        float dd[4] = {w.x, w.y, w.z, w.w};

        unsigned t[4];
#pragma unroll
        for (int k = 0; k < 4; k++) {
            unsigned sa = SMEM_TBL ? spec_smem(tbl, i1[k]) : spec_gmem(i1[k]);
            unsigned sb = SMEM_TBL ? spec_smem(tbl, i2[k]) : spec_gmem(i2[k]);
            t[k] = sa * 4u + sb;
        }

#pragma unroll
        for (int k = 0; k < 4; k++) {
            float d  = dd[k] * A2B;
            float x2 = d * d * inv_rc2;
            if (x2 < 1.0f) {
                float E   = fmaf(s_df[t[k]], d, 1.0f - __fdividef(1.0f, 1.0f - x2));
                float srb = s_pre[t[k]] * __expf(E);
                unsigned mol = POW2 ? ((unsigned)i1[k] >> shift)
                                    : ((unsigned)i1[k] / (unsigned)n_atoms);
                atomicAdd(&hist[mol], srb);
            }
        }
    }

    // scalar tail
    if (blockIdx.x == 0) {
        for (int p = nvec * 4 + threadIdx.x; p < n_pairs; p += BLOCK) {
            int   i1 = idx12[p];
            int   i2 = idx12[p + n_pairs];
            float d  = dist[p] * A2B;
            unsigned sa = SMEM_TBL ? spec_smem(tbl, i1) : spec_gmem(i1);
            unsigned sb = SMEM_TBL ? spec_smem(tbl, i2) : spec_gmem(i2);
            unsigned tt = sa * 4u + sb;
            float x2 = d * d * inv_rc2;
            if (x2 < 1.0f) {
                float E   = fmaf(s_df[tt], d, 1.0f - __fdividef(1.0f, 1.0f - x2));
                float srb = s_pre[tt] * __expf(E);
                unsigned mol = POW2 ? ((unsigned)i1 >> shift)
                                    : ((unsigned)i1 / (unsigned)n_atoms);
                atomicAdd(&hist[mol], srb);
            }
        }
    }
    __syncthreads();

    for (int i = threadIdx.x; i < n_mol; i += BLOCK) {
        float v = hist[i];
        if (v != 0.0f) atomicAdd(&out_energy[i], v);
    }
}

// ---------------------------------------------------------------------------
extern "C" void kernel_launch(void* const* d_in, const int* in_sizes, int n_in,
                              void* d_out, int out_size) {
    const int*   species  = (const int*)  d_in[0];
    const float* energies = (const float*)d_in[1];
    const int*   idx12    = (const int*)  d_in[2];
    const float* dist     = (const float*)d_in[3];
    const float* ep       = (const float*)d_in[4];
    const float* df       = (const float*)d_in[5];

    int n_species = in_sizes[0];
    int n_mol     = in_sizes[1];
    int n_pairs   = in_sizes[3];
    int n_atoms   = n_species / n_mol;
    int n_words   = (n_species + 15) >> 4;

    int with_species = (out_size > n_mol) ? 1 : 0;
    float* out        = (float*)d_out;
    float* out_energy = with_species ? (out + n_species) : out;

    int shift = -1;
    if (n_atoms > 0 && (n_atoms & (n_atoms - 1)) == 0) {
        shift = 0;
        int v = n_atoms;
        while (v > 1) { v >>= 1; shift++; }
    }

    int prep_n = (n_species > n_mol ? n_species : n_mol);
    prep_kernel<<<(prep_n + 255) / 256, 256>>>(species, energies, out,
                                               n_species, n_mol, with_species);

    // smem budget: hist + table; need 2 CTAs/SM -> each <= ~96KB
    size_t dyn_tbl = (size_t)MAX_MOL * 4 + (size_t)n_words * 4;
    bool use_smem_tbl = (n_mol <= MAX_MOL) && (dyn_tbl <= 96 * 1024);

    if (use_smem_tbl) {
        if (shift >= 0) {
            cudaFuncSetAttribute(srb_kernel<true, true>,
                                 cudaFuncAttributeMaxDynamicSharedMemorySize,
                                 (int)dyn_tbl);
            srb_kernel<true, true><<<GRID, BLOCK, dyn_tbl>>>(
                idx12, dist, ep, df, out_energy, n_pairs, shift, n_atoms, n_mol, n_words);
        } else {
            cudaFuncSetAttribute(srb_kernel<false, true>,
                                 cudaFuncAttributeMaxDynamicSharedMemorySize,
                                 (int)dyn_tbl);
            srb_kernel<false, true><<<GRID, BLOCK, dyn_tbl>>>(
                idx12, dist, ep, df, out_energy, n_pairs, shift, n_atoms, n_mol, n_words);
        }
    } else {
        size_t dyn = (size_t)MAX_MOL * 4;
        if (shift >= 0)
            srb_kernel<true, false><<<GRID, BLOCK, dyn>>>(
                idx12, dist, ep, df, out_energy, n_pairs, shift, n_atoms, n_mol, n_words);
        else
            srb_kernel<false, false><<<GRID, BLOCK, dyn>>>(
                idx12, dist, ep, df, out_energy, n_pairs, shift, n_atoms, n_mol, n_words);
    }
}

// round 7
// speedup vs baseline: 7.4759x; 1.0340x over previous
#include <cuda_runtime.h>
#include <cuda_bf16.h>

#define BLOCK 1024
#define GRID  304            // 152 SMs * 2 CTAs
#define MAX_MOL 4096
#define PACK_WORDS_CAP (1 << 20)     // u32 words; 16 atoms/word -> up to 16M atoms

__device__ unsigned g_packed[PACK_WORDS_CAP];

// ---------------------------------------------------------------------------
// Prep: pack species (0..3) into 2-bit entries (16/word) AND init output.
//   Layout A (out_size > n_mol): [species as float (n_species)] [energies]
//   Layout B: [energies]
// ---------------------------------------------------------------------------
__global__ void prep_kernel(const int* __restrict__ sp,
                            const float* __restrict__ energies,
                            float* __restrict__ out,
                            int n_species, int n_mol, int with_species) {
    int i = blockIdx.x * blockDim.x + threadIdx.x;
    int n_words = (n_species + 15) >> 4;

    if (i < n_words) {
        int base = i * 16;
        unsigned v = 0;
        if (base + 16 <= n_species) {
            const int4* p = (const int4*)(sp + base);
#pragma unroll
            for (int q = 0; q < 4; q++) {
                int4 s = p[q];
                v |= ((unsigned)s.x & 3u) << (2 * (q * 4 + 0));
                v |= ((unsigned)s.y & 3u) << (2 * (q * 4 + 1));
                v |= ((unsigned)s.z & 3u) << (2 * (q * 4 + 2));
                v |= ((unsigned)s.w & 3u) << (2 * (q * 4 + 3));
            }
        } else {
            for (int k = 0; k < 16 && base + k < n_species; k++)
                v |= ((unsigned)sp[base + k] & 3u) << (2 * k);
        }
        g_packed[i] = v;
    }

    if (with_species) {
        if (i < n_species) out[i] = (float)sp[i];
        if (i < n_mol)     out[n_species + i] = energies[i];
    } else {
        if (i < n_mol)     out[i] = energies[i];
    }
}

// ---------------------------------------------------------------------------
// Main kernel. Dynamic smem: [ hist: MAX_MOL floats ][ tbl: n_words u32 ]
// Static smem: fused (pre, df) float2 table, 16 entries.
// ---------------------------------------------------------------------------
template <bool POW2, bool SMEM_TBL>
__global__ __launch_bounds__(BLOCK, 2) void srb_kernel(
    const int*   __restrict__ idx12,
    const float* __restrict__ dist,
    const float* __restrict__ ep,
    const float* __restrict__ df,
    float*       __restrict__ out_energy,
    int n_pairs, int shift, int n_atoms, int n_mol, int n_words)
{
    extern __shared__ unsigned char smem_raw[];
    float*    hist = (float*)smem_raw;
    unsigned* tbl  = (unsigned*)(smem_raw + MAX_MOL * sizeof(float));

    __shared__ float2 s_tab[16];   // (pre, df)

    if (threadIdx.x < 16)
        s_tab[threadIdx.x] = make_float2(ep[threadIdx.x], df[threadIdx.x]);
    for (int i = threadIdx.x; i < MAX_MOL; i += BLOCK) hist[i] = 0.0f;
    if (SMEM_TBL) {
        for (int i = threadIdx.x; i < n_words; i += BLOCK)
            tbl[i] = g_packed[i];
    }
    __syncthreads();

    const float A2B     = 1.8897261258369282f;
    const float rc      = 5.2f * A2B;
    const float inv_rc2 = 1.0f / (rc * rc);

    const int nvec = n_pairs >> 2;
    const int4*   iv1 = (const int4*)idx12;
    const int4*   iv2 = (const int4*)(idx12 + n_pairs);
    const float4* dv  = (const float4*)dist;

    const int stride = GRID * BLOCK;
    for (int p = blockIdx.x * BLOCK + threadIdx.x; p < nvec; p += stride) {
        int4   a = __ldcs(&iv1[p]);
        int4   b = __ldcs(&iv2[p]);
        float4 w = __ldcs(&dv[p]);

        int   i1[4] = {a.x, a.y, a.z, a.w};
        int   i2[4] = {b.x, b.y, b.z, b.w};
        float dd[4] = {w.x, w.y, w.z, w.w};

#pragma unroll
        for (int k = 0; k < 4; k++) {
            float d  = dd[k] * A2B;
            float x2 = d * d * inv_rc2;
            if (x2 < 1.0f) {
                unsigned u1 = (unsigned)i1[k];
                unsigned u2 = (unsigned)i2[k];
                unsigned w1 = SMEM_TBL ? tbl[u1 >> 4] : __ldg(&g_packed[u1 >> 4]);
                unsigned w2 = SMEM_TBL ? tbl[u2 >> 4] : __ldg(&g_packed[u2 >> 4]);
                unsigned sa = (w1 >> ((u1 & 15u) * 2u)) & 3u;
                unsigned sb = (w2 >> ((u2 & 15u) * 2u)) & 3u;
                float2 c = s_tab[sa * 4u + sb];
                float  E = fmaf(c.y, d, 1.0f - __fdividef(1.0f, 1.0f - x2));
                unsigned mol = POW2 ? (u1 >> shift) : (u1 / (unsigned)n_atoms);
                atomicAdd(&hist[mol], c.x * __expf(E));
            }
        }
    }

    // scalar tail
    if (blockIdx.x == 0) {
        for (int p = nvec * 4 + threadIdx.x; p < n_pairs; p += BLOCK) {
            unsigned u1 = (unsigned)idx12[p];
            unsigned u2 = (unsigned)idx12[p + n_pairs];
            float d  = dist[p] * A2B;
            float x2 = d * d * inv_rc2;
            if (x2 < 1.0f) {
                unsigned w1 = SMEM_TBL ? tbl[u1 >> 4] : __ldg(&g_packed[u1 >> 4]);
                unsigned w2 = SMEM_TBL ? tbl[u2 >> 4] : __ldg(&g_packed[u2 >> 4]);
                unsigned sa = (w1 >> ((u1 & 15u) * 2u)) & 3u;
                unsigned sb = (w2 >> ((u2 & 15u) * 2u)) & 3u;
                float2 c = s_tab[sa * 4u + sb];
                float  E = fmaf(c.y, d, 1.0f - __fdividef(1.0f, 1.0f - x2));
                unsigned mol = POW2 ? (u1 >> shift) : (u1 / (unsigned)n_atoms);
                atomicAdd(&hist[mol], c.x * __expf(E));
            }
        }
    }
    __syncthreads();

    for (int i = threadIdx.x; i < n_mol; i += BLOCK) {
        float v = hist[i];
        if (v != 0.0f) atomicAdd(&out_energy[i], v);
    }
}

// ---------------------------------------------------------------------------
extern "C" void kernel_launch(void* const* d_in, const int* in_sizes, int n_in,
                              void* d_out, int out_size) {
    const int*   species  = (const int*)  d_in[0];
    const float* energies = (const float*)d_in[1];
    const int*   idx12    = (const int*)  d_in[2];
    const float* dist     = (const float*)d_in[3];
    const float* ep       = (const float*)d_in[4];
    const float* df       = (const float*)d_in[5];

    int n_species = in_sizes[0];
    int n_mol     = in_sizes[1];
    int n_pairs   = in_sizes[3];
    int n_atoms   = n_species / n_mol;
    int n_words   = (n_species + 15) >> 4;

    int with_species = (out_size > n_mol) ? 1 : 0;
    float* out        = (float*)d_out;
    float* out_energy = with_species ? (out + n_species) : out;

    int shift = -1;
    if (n_atoms > 0 && (n_atoms & (n_atoms - 1)) == 0) {
        shift = 0;
        int v = n_atoms;
        while (v > 1) { v >>= 1; shift++; }
    }

    int prep_n = (n_species > n_mol ? n_species : n_mol);
    prep_kernel<<<(prep_n + 255) / 256, 256>>>(species, energies, out,
                                               n_species, n_mol, with_species);

    size_t dyn_tbl = (size_t)MAX_MOL * 4 + (size_t)n_words * 4;
    bool use_smem_tbl = (n_mol <= MAX_MOL) && (dyn_tbl <= 96 * 1024);

    if (use_smem_tbl) {
        if (shift >= 0) {
            cudaFuncSetAttribute(srb_kernel<true, true>,
                                 cudaFuncAttributeMaxDynamicSharedMemorySize,
                                 (int)dyn_tbl);
            srb_kernel<true, true><<<GRID, BLOCK, dyn_tbl>>>(
                idx12, dist, ep, df, out_energy, n_pairs, shift, n_atoms, n_mol, n_words);
        } else {
            cudaFuncSetAttribute(srb_kernel<false, true>,
                                 cudaFuncAttributeMaxDynamicSharedMemorySize,
                                 (int)dyn_tbl);
            srb_kernel<false, true><<<GRID, BLOCK, dyn_tbl>>>(
                idx12, dist, ep, df, out_energy, n_pairs, shift, n_atoms, n_mol, n_words);
        }
    } else {
        size_t dyn = (size_t)MAX_MOL * 4;
        if (shift >= 0)
            srb_kernel<true, false><<<GRID, BLOCK, dyn>>>(
                idx12, dist, ep, df, out_energy, n_pairs, shift, n_atoms, n_mol, n_words);
        else
            srb_kernel<false, false><<<GRID, BLOCK, dyn>>>(
                idx12, dist, ep, df, out_energy, n_pairs, shift, n_atoms, n_mol, n_words);
    }
}